// round 1
// baseline (speedup 1.0000x reference)
#include <cuda_runtime.h>
#include <math.h>

// Problem constants
#define TT 256      // timesteps
#define BB 256      // batch
#define DD 1024     // hidden dim
#define WSTRIDE 2048  // W is (D, 2D) row-major

// ---------------------------------------------------------------------------
// Kernel 1: out[(b*TT + t)*DD + d] = bias[d] + sum_k x[(t*BB+b)*DD + k] * W[d*WSTRIDE + k]
// Classic smem-tiled fp32 GEMM. M = TT*BB = 65536 rows (row r = t*BB + b),
// N = DD, K = DD. Output rows are scattered: r=(t,b) -> out row (b*TT + t).
// ---------------------------------------------------------------------------
#define K1_BM 64
#define K1_BN 64
#define K1_BK 16

__global__ void __launch_bounds__(256)
gemm_x_kernel(const float* __restrict__ x, const float* __restrict__ W,
              const float* __restrict__ bias, float* __restrict__ out)
{
    __shared__ __align__(16) float sA[K1_BK][K1_BM];
    __shared__ __align__(16) float sB[K1_BK][K1_BN];

    const int r0  = blockIdx.y * K1_BM;   // row tile in (t*BB + b) space
    const int d0  = blockIdx.x * K1_BN;   // col tile in d
    const int tid = threadIdx.x;
    const int tx  = tid & 15;             // 16 threads across N
    const int ty  = tid >> 4;             // 16 threads across M

    float acc[4][4] = {};

    for (int k0 = 0; k0 < DD; k0 += K1_BK) {
        // Load A tile (64x16), 4 floats/thread, vectorized float4 along k
        {
            const int lin = tid * 4;          // 1024 floats total
            const int i   = lin >> 4;         // row within tile
            const int k   = lin & 15;         // k within tile (multiple of 4)
            const float4 v = *reinterpret_cast<const float4*>(
                &x[(size_t)(r0 + i) * DD + k0 + k]);
            sA[k + 0][i] = v.x;
            sA[k + 1][i] = v.y;
            sA[k + 2][i] = v.z;
            sA[k + 3][i] = v.w;
        }
        // Load B tile (Wx^T view): sB[k][d] from W[d*WSTRIDE + k]
        {
            const int lin = tid * 4;
            const int dd  = lin >> 4;
            const int k   = lin & 15;
            const float4 v = *reinterpret_cast<const float4*>(
                &W[(size_t)(d0 + dd) * WSTRIDE + k0 + k]);
            sB[k + 0][dd] = v.x;
            sB[k + 1][dd] = v.y;
            sB[k + 2][dd] = v.z;
            sB[k + 3][dd] = v.w;
        }
        __syncthreads();

        #pragma unroll
        for (int k = 0; k < K1_BK; ++k) {
            const float4 av = *reinterpret_cast<const float4*>(&sA[k][ty * 4]);
            const float4 bv = *reinterpret_cast<const float4*>(&sB[k][tx * 4]);
            const float a_[4] = {av.x, av.y, av.z, av.w};
            const float b_[4] = {bv.x, bv.y, bv.z, bv.w};
            #pragma unroll
            for (int mi = 0; mi < 4; ++mi)
                #pragma unroll
                for (int ni = 0; ni < 4; ++ni)
                    acc[mi][ni] += a_[mi] * b_[ni];
        }
        __syncthreads();
    }

    // Epilogue: scatter to out[b][t][d] with bias
    #pragma unroll
    for (int mi = 0; mi < 4; ++mi) {
        const int r = r0 + ty * 4 + mi;
        const int t = r >> 8;      // r / BB
        const int b = r & 255;     // r % BB
        float* orow = out + ((size_t)(b * TT + t)) * DD + d0 + tx * 4;
        #pragma unroll
        for (int ni = 0; ni < 4; ++ni)
            orow[ni] = acc[mi][ni] + bias[d0 + tx * 4 + ni];
    }
}

// ---------------------------------------------------------------------------
// t = 0: h0 = 0, so out slice is just tanh of the preactivation
// ---------------------------------------------------------------------------
__global__ void __launch_bounds__(256)
tanh0_kernel(float* __restrict__ out)
{
    const int idx = blockIdx.x * blockDim.x + threadIdx.x;  // over BB*DD
    const int b = idx >> 10;          // idx / DD
    const int d = idx & 1023;         // idx % DD
    float* p = out + ((size_t)(b * TT)) * DD + d;  // t = 0
    *p = tanhf(*p);
}

// ---------------------------------------------------------------------------
// Step kernel (t >= 1):
//   out[(b*TT + t)*DD + d] = tanh( out[(b*TT+t)*DD+d]  (preactivation A)
//                                 + sum_k out[(b*TT+t-1)*DD+k] * W[d*WSTRIDE + DD + k] )
// GEMM: M = BB = 256 (batch), N = DD, K = DD.
// 128 blocks/step (16 x 8), 256 threads, 2x4 outputs/thread.
// ---------------------------------------------------------------------------
#define K2_BM 32
#define K2_BN 64
#define K2_BK 16

__global__ void __launch_bounds__(256)
step_kernel(const float* __restrict__ W, float* __restrict__ out, int t)
{
    __shared__ __align__(16) float sA[K2_BK][K2_BM];
    __shared__ __align__(16) float sB[K2_BK][K2_BN];

    const int b0  = blockIdx.y * K2_BM;   // batch tile
    const int d0  = blockIdx.x * K2_BN;   // output-dim tile
    const int tid = threadIdx.x;
    const int tx  = tid & 15;
    const int ty  = tid >> 4;

    const float* Wh = W + DD;  // Wh[d][k] = W[d*WSTRIDE + DD + k]

    float acc[2][4] = {};

    for (int k0 = 0; k0 < DD; k0 += K2_BK) {
        // Load h_{t-1} tile (32x16), 2 floats/thread via float2
        {
            const int lin = tid * 2;          // 512 floats total
            const int i   = lin >> 4;
            const int k   = lin & 15;         // multiple of 2
            const float2 v = *reinterpret_cast<const float2*>(
                &out[((size_t)((b0 + i) * TT + (t - 1))) * DD + k0 + k]);
            sA[k + 0][i] = v.x;
            sA[k + 1][i] = v.y;
        }
        // Load Wh tile (64x16), 4 floats/thread via float4
        {
            const int lin = tid * 4;
            const int dd  = lin >> 4;
            const int k   = lin & 15;
            const float4 v = *reinterpret_cast<const float4*>(
                &Wh[(size_t)(d0 + dd) * WSTRIDE + k0 + k]);
            sB[k + 0][dd] = v.x;
            sB[k + 1][dd] = v.y;
            sB[k + 2][dd] = v.z;
            sB[k + 3][dd] = v.w;
        }
        __syncthreads();

        #pragma unroll
        for (int k = 0; k < K2_BK; ++k) {
            const float2 av = *reinterpret_cast<const float2*>(&sA[k][ty * 2]);
            const float4 bv = *reinterpret_cast<const float4*>(&sB[k][tx * 4]);
            const float a_[2] = {av.x, av.y};
            const float b_[4] = {bv.x, bv.y, bv.z, bv.w};
            #pragma unroll
            for (int mi = 0; mi < 2; ++mi)
                #pragma unroll
                for (int ni = 0; ni < 4; ++ni)
                    acc[mi][ni] += a_[mi] * b_[ni];
        }
        __syncthreads();
    }

    // Epilogue: add preactivation already in out, tanh, store in place
    #pragma unroll
    for (int mi = 0; mi < 2; ++mi) {
        const int b = b0 + ty * 2 + mi;
        float* orow = out + ((size_t)(b * TT + t)) * DD + d0 + tx * 4;
        #pragma unroll
        for (int ni = 0; ni < 4; ++ni)
            orow[ni] = tanhf(orow[ni] + acc[mi][ni]);
    }
}

// ---------------------------------------------------------------------------
// Launch
// ---------------------------------------------------------------------------
extern "C" void kernel_launch(void* const* d_in, const int* in_sizes, int n_in,
                              void* d_out, int out_size)
{
    const float* x    = (const float*)d_in[0];
    const float* W    = (const float*)d_in[1];
    const float* bias = (const float*)d_in[2];
    float* out = (float*)d_out;

    // 1) Preactivations for all timesteps, written to out[b][t][:]
    dim3 g1(DD / K1_BN, (TT * BB) / K1_BM);   // (16, 1024)
    gemm_x_kernel<<<g1, 256>>>(x, W, bias, out);

    // 2) t = 0: tanh only (h0 = 0)
    tanh0_kernel<<<(BB * DD) / 256, 256>>>(out);

    // 3) Sequential recurrence
    dim3 g2(DD / K2_BN, BB / K2_BM);          // (16, 8) = 128 blocks
    for (int t = 1; t < TT; ++t)
        step_kernel<<<g2, 256>>>(W, out, t);
}

// round 2
// speedup vs baseline: 1.8518x; 1.8518x over previous
#include <cuda_runtime.h>
#include <mma.h>
#include <math.h>

using namespace nvcuda;

#define TT 256      // timesteps
#define BB 256      // batch
#define DD 1024     // hidden dim
#define WS 2048     // W row stride (W is (D, 2D) row-major)

// ===========================================================================
// Kernel 1: preactivations via tf32 wmma
//   out[(b*TT + t)*DD + d] = bias[d] + sum_k x[(t*BB+b)*DD + k] * W[d*WS + k]
//   M = TT*BB = 65536 (row r = t*BB + b), N = DD, K = DD
// ===========================================================================
#define X_BM 64
#define X_BN 64
#define X_BK 32
#define X_LD 40   // padded smem leading dim (multiple of 4, 160B rows)

__global__ void __launch_bounds__(256)
gemm_x_tf32(const float* __restrict__ x, const float* __restrict__ W,
            const float* __restrict__ bias, float* __restrict__ out)
{
    __shared__ __align__(16) float buf[2 * X_BM * X_LD];  // 5120 floats (20 KB)
    float* sA = buf;                   // 64 x 40
    float* sB = buf + X_BM * X_LD;     // 64 x 40

    const int r0  = blockIdx.y * X_BM;
    const int d0  = blockIdx.x * X_BN;
    const int tid = threadIdx.x;
    const int wid = tid >> 5;
    const int warpM = wid >> 1;        // 0..3
    const int warpN = wid & 1;         // 0..1 (each warp: 16x32)

    wmma::fragment<wmma::accumulator, 16, 16, 8, float> acc[2];
    wmma::fill_fragment(acc[0], 0.0f);
    wmma::fill_fragment(acc[1], 0.0f);

    for (int k0 = 0; k0 < DD; k0 += X_BK) {
        // A tile: 64 rows x 32 k  (512 float4, 2 per thread)
        #pragma unroll
        for (int j = 0; j < 2; ++j) {
            int f   = tid + j * 256;
            int row = f >> 3;          // 8 float4 per row
            int c4  = f & 7;
            float4 v = *reinterpret_cast<const float4*>(
                &x[(size_t)(r0 + row) * DD + k0 + c4 * 4]);
            float* p = &sA[row * X_LD + c4 * 4];
            p[0] = v.x; p[1] = v.y; p[2] = v.z; p[3] = v.w;
        }
        // B tile: Wx[d][k] = W[d*WS + k], 64 x 32
        #pragma unroll
        for (int j = 0; j < 2; ++j) {
            int f   = tid + j * 256;
            int row = f >> 3;
            int c4  = f & 7;
            float4 v = *reinterpret_cast<const float4*>(
                &W[(size_t)(d0 + row) * WS + k0 + c4 * 4]);
            float* p = &sB[row * X_LD + c4 * 4];
            p[0] = v.x; p[1] = v.y; p[2] = v.z; p[3] = v.w;
        }
        __syncthreads();

        #pragma unroll
        for (int kk = 0; kk < X_BK; kk += 8) {
            wmma::fragment<wmma::matrix_a, 16, 16, 8, wmma::precision::tf32, wmma::row_major> a;
            wmma::load_matrix_sync(a, &sA[warpM * 16 * X_LD + kk], X_LD);
            #pragma unroll
            for (int i = 0; i < a.num_elements; ++i) a.x[i] = wmma::__float_to_tf32(a.x[i]);
            #pragma unroll
            for (int nn = 0; nn < 2; ++nn) {
                wmma::fragment<wmma::matrix_b, 16, 16, 8, wmma::precision::tf32, wmma::col_major> b;
                wmma::load_matrix_sync(b, &sB[(warpN * 32 + nn * 16) * X_LD + kk], X_LD);
                #pragma unroll
                for (int i = 0; i < b.num_elements; ++i) b.x[i] = wmma::__float_to_tf32(b.x[i]);
                wmma::mma_sync(acc[nn], a, b, acc[nn]);
            }
        }
        __syncthreads();
    }

    // Stage C in smem (reuse buf: need 64x64 = 4096 <= 5120 floats)
    float* sC = buf;
    wmma::store_matrix_sync(&sC[(warpM * 16) * X_BN + warpN * 32],      acc[0], X_BN, wmma::mem_row_major);
    wmma::store_matrix_sync(&sC[(warpM * 16) * X_BN + warpN * 32 + 16], acc[1], X_BN, wmma::mem_row_major);
    __syncthreads();

    // Epilogue: + bias, scatter r=(t,b) -> out row (b*TT + t)
    #pragma unroll
    for (int j = 0; j < 4; ++j) {
        int f   = tid + j * 256;       // 1024 float4
        int row = f >> 4;              // 16 float4 per row
        int c4  = f & 15;
        int r = r0 + row;
        int t = r >> 8;                // r / BB
        int b = r & 255;               // r % BB
        float4 bv = *reinterpret_cast<const float4*>(&bias[d0 + c4 * 4]);
        const float* cp = &sC[row * X_BN + c4 * 4];
        float4 o;
        o.x = cp[0] + bv.x; o.y = cp[1] + bv.y; o.z = cp[2] + bv.z; o.w = cp[3] + bv.w;
        *reinterpret_cast<float4*>(&out[((size_t)(b * TT + t)) * DD + d0 + c4 * 4]) = o;
    }
}

// ===========================================================================
// Kernel 2: persistent recurrence. 128 co-resident blocks (<= 148 SMs),
// grid barrier per timestep. Block owns out tile (b0..b0+31, d0..d0+63).
//   h_t = tanh(preact_t + h_{t-1} @ Wh^T), preact already in out.
// ===========================================================================
#define R_BM 32
#define R_BN 64
#define R_BK 64
#define R_LD 72      // padded smem leading dim
#define R_NBLK 128

__device__ unsigned g_cnt = 0;
__device__ unsigned g_phase = 0;   // monotonic across graph replays

__global__ void __launch_bounds__(256)
rnn_persistent(const float* __restrict__ W, float* __restrict__ out)
{
    __shared__ __align__(16) float sA[R_BM * R_LD];  // 32x72 (h tile / C tile)
    __shared__ __align__(16) float sB[R_BN * R_LD];  // 64x72 (Wh tile)
    __shared__ unsigned s_base;

    const int tid = threadIdx.x;
    const int wid = tid >> 5;
    const int warpM = wid & 1;       // 2 M-tiles of 16
    const int warpN = wid >> 1;      // 4 N-tiles of 16

    const int nT = blockIdx.x & 15;  // 16 n tiles
    const int mT = blockIdx.x >> 4;  // 8 m tiles
    const int d0 = nT * R_BN;
    const int b0 = mT * R_BM;

    const float* Wh = W + DD;        // Wh[d][k] = W[d*WS + DD + k]

    // Phase base: stable because no barrier can complete before every block
    // (including this one) has read it.
    if (tid == 0) s_base = *(volatile unsigned*)&g_phase;
    __syncthreads();
    const unsigned base = s_base;

    for (int t = 0; t < TT; ++t) {
        if (t == 0) {
            // h0 = 0: out slice = tanh(preact)
            #pragma unroll
            for (int j = 0; j < 2; ++j) {
                int f   = tid + j * 256;   // 512 float4
                int row = f >> 4;
                int c4  = f & 15;
                float* p = &out[((size_t)((b0 + row) * TT + 0)) * DD + d0 + c4 * 4];
                float4 v = __ldcg(reinterpret_cast<const float4*>(p));
                v.x = tanhf(v.x); v.y = tanhf(v.y); v.z = tanhf(v.z); v.w = tanhf(v.w);
                *reinterpret_cast<float4*>(p) = v;
            }
        } else {
            wmma::fragment<wmma::accumulator, 16, 16, 8, float> acc;
            wmma::fill_fragment(acc, 0.0f);

            for (int k0 = 0; k0 < DD; k0 += R_BK) {
                // A: h_{t-1}(b0..b0+31, k0..k0+63) via L2 (skip L1: written by peers)
                #pragma unroll
                for (int j = 0; j < 2; ++j) {
                    int f   = tid + j * 256;   // 512 float4
                    int row = f >> 4;          // 16 float4 per row
                    int c4  = f & 15;
                    float4 v = __ldcg(reinterpret_cast<const float4*>(
                        &out[((size_t)((b0 + row) * TT + (t - 1))) * DD + k0 + c4 * 4]));
                    float* p = &sA[row * R_LD + c4 * 4];
                    p[0] = v.x; p[1] = v.y; p[2] = v.z; p[3] = v.w;
                }
                // B: Wh(d0..d0+63, k0..k0+63), L1-cacheable (reused every step)
                #pragma unroll
                for (int j = 0; j < 4; ++j) {
                    int f   = tid + j * 256;   // 1024 float4
                    int row = f >> 4;
                    int c4  = f & 15;
                    float4 v = *reinterpret_cast<const float4*>(
                        &Wh[(size_t)(d0 + row) * WS + k0 + c4 * 4]);
                    float* p = &sB[row * R_LD + c4 * 4];
                    p[0] = v.x; p[1] = v.y; p[2] = v.z; p[3] = v.w;
                }
                __syncthreads();

                #pragma unroll
                for (int kk = 0; kk < R_BK; kk += 8) {
                    wmma::fragment<wmma::matrix_a, 16, 16, 8, wmma::precision::tf32, wmma::row_major> a;
                    wmma::fragment<wmma::matrix_b, 16, 16, 8, wmma::precision::tf32, wmma::col_major> b;
                    wmma::load_matrix_sync(a, &sA[warpM * 16 * R_LD + kk], R_LD);
                    wmma::load_matrix_sync(b, &sB[warpN * 16 * R_LD + kk], R_LD);
                    #pragma unroll
                    for (int i = 0; i < a.num_elements; ++i) a.x[i] = wmma::__float_to_tf32(a.x[i]);
                    #pragma unroll
                    for (int i = 0; i < b.num_elements; ++i) b.x[i] = wmma::__float_to_tf32(b.x[i]);
                    wmma::mma_sync(acc, a, b, acc);
                }
                __syncthreads();
            }

            // Epilogue: C -> smem, then + preact, tanh, store in place
            wmma::store_matrix_sync(&sA[(warpM * 16) * R_BN + warpN * 16], acc,
                                    R_BN, wmma::mem_row_major);
            __syncthreads();
            #pragma unroll
            for (int j = 0; j < 2; ++j) {
                int f   = tid + j * 256;
                int row = f >> 4;
                int c4  = f & 15;
                float* p = &out[((size_t)((b0 + row) * TT + t)) * DD + d0 + c4 * 4];
                float4 pre = __ldcg(reinterpret_cast<const float4*>(p));
                const float* cp = &sA[row * R_BN + c4 * 4];
                float4 o;
                o.x = tanhf(pre.x + cp[0]);
                o.y = tanhf(pre.y + cp[1]);
                o.z = tanhf(pre.z + cp[2]);
                o.w = tanhf(pre.w + cp[3]);
                *reinterpret_cast<float4*>(p) = o;
            }
        }

        // Grid barrier (skip after the last step). Leaves g_cnt = 0 on exit,
        // g_phase monotonic -> deterministic across graph replays.
        if (t != TT - 1) {
            __syncthreads();
            if (tid == 0) {
                __threadfence();                      // publish this step's h
                unsigned old = atomicAdd(&g_cnt, 1);
                if (old == R_NBLK - 1) {
                    atomicExch(&g_cnt, 0);
                    __threadfence();
                    atomicAdd(&g_phase, 1);           // release
                } else {
                    unsigned target = base + (unsigned)(t + 1);
                    while (*(volatile unsigned*)&g_phase < target) { }
                    __threadfence();                  // acquire peers' h
                }
            }
            __syncthreads();
        }
    }
}

// ===========================================================================
// Launch
// ===========================================================================
extern "C" void kernel_launch(void* const* d_in, const int* in_sizes, int n_in,
                              void* d_out, int out_size)
{
    const float* x    = (const float*)d_in[0];
    const float* W    = (const float*)d_in[1];
    const float* bias = (const float*)d_in[2];
    float* out = (float*)d_out;

    dim3 g1(DD / X_BN, (TT * BB) / X_BM);   // (16, 1024)
    gemm_x_tf32<<<g1, 256>>>(x, W, bias, out);

    rnn_persistent<<<R_NBLK, 256>>>(W, out);
}